// round 2
// baseline (speedup 1.0000x reference)
#include <cuda_runtime.h>
#include <math.h>

// Problem constants
#define NROWS 1024
#define NCLS  100000
#define DIM   512
#define NCB   782            // ceil(100000/128)
#define SCALE 64.0f
#define MARG  0.5f
#define COS_M 0.87758256189037271611f
#define SIN_M 0.47942553860420300027f
#define MIN_COS (-0.87758256189037271611f)

// Scratch (device globals: no allocation allowed)
__device__ float g_fn[NROWS * DIM];          // normalized feats
__device__ float g_winv[NCLS + 64];          // 1/max(||w_c||, eps)
__device__ float g_partial[NCB * NROWS];     // partial sumexp, [cb][n] layout
__device__ float g_cos_t[NROWS];             // cos at label column
__device__ float g_tgt[NROWS];               // margin-adjusted target logit (pre-scale)

// ---------------------------------------------------------------------------
// Kernel 1: normalize feats rows. grid=1024 blocks x 128 threads.
__global__ void k_norm_feats(const float* __restrict__ feats) {
    int row = blockIdx.x;
    int t = threadIdx.x;
    const float* x = feats + row * DIM;
    float v[4];
    float ss = 0.f;
#pragma unroll
    for (int i = 0; i < 4; i++) { v[i] = x[t + i * 128]; ss += v[i] * v[i]; }
#pragma unroll
    for (int off = 16; off > 0; off >>= 1) ss += __shfl_xor_sync(0xffffffffu, ss, off);
    __shared__ float sred[4];
    __shared__ float srinv;
    int lane = t & 31, wp = t >> 5;
    if (lane == 0) sred[wp] = ss;
    __syncthreads();
    if (t == 0) {
        float tot = sred[0] + sred[1] + sred[2] + sred[3];
        srinv = 1.f / fmaxf(sqrtf(tot), 1e-12f);
    }
    __syncthreads();
    float rinv = srinv;
#pragma unroll
    for (int i = 0; i < 4; i++) g_fn[row * DIM + t + i * 128] = v[i] * rinv;
}

// ---------------------------------------------------------------------------
// Kernel 2: inverse norms of W rows. One warp per row. grid=12500 x 256.
__global__ void k_winv(const float* __restrict__ w) {
    int wp = threadIdx.x >> 5, lane = threadIdx.x & 31;
    int row = blockIdx.x * 8 + wp;
    if (row >= NCLS) return;
    const float* x = w + (size_t)row * DIM;
    float ss = 0.f;
#pragma unroll
    for (int i = 0; i < 16; i++) { float v = x[lane + i * 32]; ss += v * v; }
#pragma unroll
    for (int off = 16; off > 0; off >>= 1) ss += __shfl_xor_sync(0xffffffffu, ss, off);
    if (lane == 0) g_winv[row] = 1.f / fmaxf(sqrtf(ss), 1e-12f);
}

// ---------------------------------------------------------------------------
// Kernel 3: main fused GEMM + exp + per-row partial sum.
// Block computes 128 rows x 128 cols tile. 256 threads, 8x8 micro-tile each.
// grid = (8 rowblocks [x, fastest -> wave shares W tiles via L2], 782 colblocks).
__global__ void __launch_bounds__(256, 2)
k_main(const float* __restrict__ w) {
    __shared__ float As[32][128];
    __shared__ float Bs[32][128];

    const int tid = threadIdx.x;
    const int tx = tid & 15;
    const int ty = tid >> 4;
    const int rowBase = blockIdx.x * 128;
    const int colBase = blockIdx.y * 128;

    float acc[8][8];
#pragma unroll
    for (int i = 0; i < 8; i++)
#pragma unroll
        for (int j = 0; j < 8; j++) acc[i][j] = 0.f;

    for (int kt = 0; kt < DIM; kt += 32) {
        // Load A (fn) and B (w) tiles, transposed into [k][row] layout.
#pragma unroll
        for (int i = 0; i < 4; i++) {
            int idx = tid + i * 256;       // 0..1023
            int r = idx >> 3;              // 0..127
            int kq = idx & 7;              // 0..7 (float4 within 32-k chunk)
            float4 va = *(const float4*)&g_fn[(rowBase + r) * DIM + kt + kq * 4];
            As[kq * 4 + 0][r] = va.x;
            As[kq * 4 + 1][r] = va.y;
            As[kq * 4 + 2][r] = va.z;
            As[kq * 4 + 3][r] = va.w;
            int c = colBase + r;
            float4 vb = make_float4(0.f, 0.f, 0.f, 0.f);
            if (c < NCLS) vb = *(const float4*)&w[(size_t)c * DIM + kt + kq * 4];
            Bs[kq * 4 + 0][r] = vb.x;
            Bs[kq * 4 + 1][r] = vb.y;
            Bs[kq * 4 + 2][r] = vb.z;
            Bs[kq * 4 + 3][r] = vb.w;
        }
        __syncthreads();
#pragma unroll 8
        for (int k = 0; k < 32; k++) {
            float4 a0 = *(const float4*)&As[k][ty * 4];
            float4 a1 = *(const float4*)&As[k][64 + ty * 4];
            float4 b0 = *(const float4*)&Bs[k][tx * 4];
            float4 b1 = *(const float4*)&Bs[k][64 + tx * 4];
            float av[8] = {a0.x, a0.y, a0.z, a0.w, a1.x, a1.y, a1.z, a1.w};
            float bv[8] = {b0.x, b0.y, b0.z, b0.w, b1.x, b1.y, b1.z, b1.w};
#pragma unroll
            for (int i = 0; i < 8; i++)
#pragma unroll
                for (int j = 0; j < 8; j++) acc[i][j] += av[i] * bv[j];
        }
        __syncthreads();
    }

    // Epilogue: cos -> clamp -> exp(S*cos - S) -> per-row tile sums.
    float rowsum[8];
#pragma unroll
    for (int i = 0; i < 8; i++) rowsum[i] = 0.f;
#pragma unroll
    for (int j = 0; j < 8; j++) {
        int cloc = (j < 4) ? (tx * 4 + j) : (64 + tx * 4 + (j - 4));
        int c = colBase + cloc;
        bool valid = (c < NCLS);
        float wv = valid ? g_winv[c] : 0.f;
#pragma unroll
        for (int i = 0; i < 8; i++) {
            float cosv = fminf(fmaxf(acc[i][j] * wv, -1.f), 1.f);
            float p = __expf(cosv * SCALE - SCALE);
            if (valid) rowsum[i] += p;
        }
    }

    // Reduce across the 16 tx groups per row, using As storage as scratch.
    float* red = &As[0][0];  // 128 rows x 16 = 2048 floats
#pragma unroll
    for (int i = 0; i < 8; i++) {
        int rloc = (i < 4) ? (ty * 4 + i) : (64 + ty * 4 + (i - 4));
        red[rloc * 16 + tx] = rowsum[i];
    }
    __syncthreads();
    if (tid < 128) {
        float s = 0.f;
#pragma unroll
        for (int t = 0; t < 16; t++) s += red[tid * 16 + t];
        g_partial[blockIdx.y * NROWS + rowBase + tid] = s;
    }
}

// ---------------------------------------------------------------------------
// Kernel 4: label-column cos + margin target. One warp per sample. grid=128x256.
__global__ void k_label(const float* __restrict__ w, const int* __restrict__ labels) {
    int wp = threadIdx.x >> 5, lane = threadIdx.x & 31;
    int n = blockIdx.x * 8 + wp;
    if (n >= NROWS) return;
    int lab = labels[n];
    const float* fr = g_fn + n * DIM;
    const float* wr = w + (size_t)lab * DIM;
    float dot = 0.f;
#pragma unroll
    for (int i = 0; i < 16; i++) dot += fr[lane + i * 32] * wr[lane + i * 32];
#pragma unroll
    for (int off = 16; off > 0; off >>= 1) dot += __shfl_xor_sync(0xffffffffu, dot, off);
    if (lane == 0) {
        float cosv = fminf(fmaxf(dot * g_winv[lab], -1.f), 1.f);
        float sinv = sqrtf(1.f - cosv * cosv + 1e-5f);
        float cm = cosv * COS_M - sinv * SIN_M;
        float tgt = (cosv > MIN_COS) ? cm : (cosv - sinv * MARG);
        g_cos_t[n] = cosv;
        g_tgt[n] = tgt;
    }
}

// ---------------------------------------------------------------------------
// Kernel 5: merge partials, fix up label column, NLL, mean. 1 block x 1024.
__global__ void k_final(float* __restrict__ out) {
    int t = threadIdx.x;
    float s = 0.f;
    // coalesced: [cb][n] layout
    for (int cb = 0; cb < NCB; cb++) s += g_partial[cb * NROWS + t];
    // replace plain label term with margin term
    float cosv = g_cos_t[t];
    float tgt = g_tgt[t];
    float s2 = s - expf(SCALE * cosv - SCALE) + expf(SCALE * tgt - SCALE);
    float nll = SCALE + logf(s2) - SCALE * tgt;   // logsumexp - target logit

    __shared__ float sred[1024];
    sred[t] = nll;
    __syncthreads();
    for (int off = 512; off > 0; off >>= 1) {
        if (t < off) sred[t] += sred[t + off];
        __syncthreads();
    }
    if (t == 0) out[0] = sred[0] * (1.0f / (float)NROWS);
}

// ---------------------------------------------------------------------------
extern "C" void kernel_launch(void* const* d_in, const int* in_sizes, int n_in,
                              void* d_out, int out_size) {
    const float* feats = (const float*)d_in[0];
    const float* w = (const float*)d_in[1];
    const int* labels = (const int*)d_in[2];
    float* out = (float*)d_out;

    k_norm_feats<<<NROWS, 128>>>(feats);
    k_winv<<<(NCLS + 7) / 8, 256>>>(w);
    k_main<<<dim3(8, NCB), 256>>>(w);
    k_label<<<NROWS / 8, 256>>>(w, labels);
    k_final<<<1, 1024>>>(out);
}

// round 3
// speedup vs baseline: 1.0006x; 1.0006x over previous
#include <cuda_runtime.h>
#include <math.h>

// Problem constants
#define NROWS 1024
#define NCLS  100000
#define DIM   512
#define NCB   782            // ceil(100000/128)
#define SCALE 64.0f
#define MARG  0.5f
#define COS_M 0.87758256189037271611f
#define SIN_M 0.47942553860420300027f
#define MIN_COS (-0.87758256189037271611f)

// Scratch (device globals: no allocation allowed)
__device__ float g_fn[NROWS * DIM];          // normalized feats
__device__ float g_winv[NCLS + 64];          // 1/max(||w_c||, eps)
__device__ float g_partial[NCB * NROWS];     // partial sumexp, [cb][n] layout
__device__ float g_cos_t[NROWS];             // cos at label column
__device__ float g_tgt[NROWS];               // margin-adjusted target logit (pre-scale)

// ---------------------------------------------------------------------------
// Kernel 1: normalize feats rows. grid=1024 blocks x 128 threads.
__global__ void k_norm_feats(const float* __restrict__ feats) {
    int row = blockIdx.x;
    int t = threadIdx.x;
    const float* x = feats + row * DIM;
    float v[4];
    float ss = 0.f;
#pragma unroll
    for (int i = 0; i < 4; i++) { v[i] = x[t + i * 128]; ss += v[i] * v[i]; }
#pragma unroll
    for (int off = 16; off > 0; off >>= 1) ss += __shfl_xor_sync(0xffffffffu, ss, off);
    __shared__ float sred[4];
    __shared__ float srinv;
    int lane = t & 31, wp = t >> 5;
    if (lane == 0) sred[wp] = ss;
    __syncthreads();
    if (t == 0) {
        float tot = sred[0] + sred[1] + sred[2] + sred[3];
        srinv = 1.f / fmaxf(sqrtf(tot), 1e-12f);
    }
    __syncthreads();
    float rinv = srinv;
#pragma unroll
    for (int i = 0; i < 4; i++) g_fn[row * DIM + t + i * 128] = v[i] * rinv;
}

// ---------------------------------------------------------------------------
// Kernel 2: inverse norms of W rows. One warp per row. grid=12500 x 256.
__global__ void k_winv(const float* __restrict__ w) {
    int wp = threadIdx.x >> 5, lane = threadIdx.x & 31;
    int row = blockIdx.x * 8 + wp;
    if (row >= NCLS) return;
    const float* x = w + (size_t)row * DIM;
    float ss = 0.f;
#pragma unroll
    for (int i = 0; i < 16; i++) { float v = x[lane + i * 32]; ss += v * v; }
#pragma unroll
    for (int off = 16; off > 0; off >>= 1) ss += __shfl_xor_sync(0xffffffffu, ss, off);
    if (lane == 0) g_winv[row] = 1.f / fmaxf(sqrtf(ss), 1e-12f);
}

// ---------------------------------------------------------------------------
// Kernel 3: main fused GEMM + exp + per-row partial sum.
// Block computes 128 rows x 128 cols tile. 256 threads, 8x8 micro-tile each.
// grid = (8 rowblocks [x, fastest -> wave shares W tiles via L2], 782 colblocks).
__global__ void __launch_bounds__(256, 2)
k_main(const float* __restrict__ w) {
    __shared__ float As[32][128];
    __shared__ float Bs[32][128];

    const int tid = threadIdx.x;
    const int tx = tid & 15;
    const int ty = tid >> 4;
    const int rowBase = blockIdx.x * 128;
    const int colBase = blockIdx.y * 128;

    float acc[8][8];
#pragma unroll
    for (int i = 0; i < 8; i++)
#pragma unroll
        for (int j = 0; j < 8; j++) acc[i][j] = 0.f;

    for (int kt = 0; kt < DIM; kt += 32) {
        // Load A (fn) and B (w) tiles, transposed into [k][row] layout.
#pragma unroll
        for (int i = 0; i < 4; i++) {
            int idx = tid + i * 256;       // 0..1023
            int r = idx >> 3;              // 0..127
            int kq = idx & 7;              // 0..7 (float4 within 32-k chunk)
            float4 va = *(const float4*)&g_fn[(rowBase + r) * DIM + kt + kq * 4];
            As[kq * 4 + 0][r] = va.x;
            As[kq * 4 + 1][r] = va.y;
            As[kq * 4 + 2][r] = va.z;
            As[kq * 4 + 3][r] = va.w;
            int c = colBase + r;
            float4 vb = make_float4(0.f, 0.f, 0.f, 0.f);
            if (c < NCLS) vb = *(const float4*)&w[(size_t)c * DIM + kt + kq * 4];
            Bs[kq * 4 + 0][r] = vb.x;
            Bs[kq * 4 + 1][r] = vb.y;
            Bs[kq * 4 + 2][r] = vb.z;
            Bs[kq * 4 + 3][r] = vb.w;
        }
        __syncthreads();
#pragma unroll 8
        for (int k = 0; k < 32; k++) {
            float4 a0 = *(const float4*)&As[k][ty * 4];
            float4 a1 = *(const float4*)&As[k][64 + ty * 4];
            float4 b0 = *(const float4*)&Bs[k][tx * 4];
            float4 b1 = *(const float4*)&Bs[k][64 + tx * 4];
            float av[8] = {a0.x, a0.y, a0.z, a0.w, a1.x, a1.y, a1.z, a1.w};
            float bv[8] = {b0.x, b0.y, b0.z, b0.w, b1.x, b1.y, b1.z, b1.w};
#pragma unroll
            for (int i = 0; i < 8; i++)
#pragma unroll
                for (int j = 0; j < 8; j++) acc[i][j] += av[i] * bv[j];
        }
        __syncthreads();
    }

    // Epilogue: cos -> clamp -> exp(S*cos - S) -> per-row tile sums.
    float rowsum[8];
#pragma unroll
    for (int i = 0; i < 8; i++) rowsum[i] = 0.f;
#pragma unroll
    for (int j = 0; j < 8; j++) {
        int cloc = (j < 4) ? (tx * 4 + j) : (64 + tx * 4 + (j - 4));
        int c = colBase + cloc;
        bool valid = (c < NCLS);
        float wv = valid ? g_winv[c] : 0.f;
#pragma unroll
        for (int i = 0; i < 8; i++) {
            float cosv = fminf(fmaxf(acc[i][j] * wv, -1.f), 1.f);
            float p = __expf(cosv * SCALE - SCALE);
            if (valid) rowsum[i] += p;
        }
    }

    // Reduce across the 16 tx groups per row, using As storage as scratch.
    float* red = &As[0][0];  // 128 rows x 16 = 2048 floats
#pragma unroll
    for (int i = 0; i < 8; i++) {
        int rloc = (i < 4) ? (ty * 4 + i) : (64 + ty * 4 + (i - 4));
        red[rloc * 16 + tx] = rowsum[i];
    }
    __syncthreads();
    if (tid < 128) {
        float s = 0.f;
#pragma unroll
        for (int t = 0; t < 16; t++) s += red[tid * 16 + t];
        g_partial[blockIdx.y * NROWS + rowBase + tid] = s;
    }
}

// ---------------------------------------------------------------------------
// Kernel 4: label-column cos + margin target. One warp per sample. grid=128x256.
__global__ void k_label(const float* __restrict__ w, const int* __restrict__ labels) {
    int wp = threadIdx.x >> 5, lane = threadIdx.x & 31;
    int n = blockIdx.x * 8 + wp;
    if (n >= NROWS) return;
    int lab = labels[n];
    const float* fr = g_fn + n * DIM;
    const float* wr = w + (size_t)lab * DIM;
    float dot = 0.f;
#pragma unroll
    for (int i = 0; i < 16; i++) dot += fr[lane + i * 32] * wr[lane + i * 32];
#pragma unroll
    for (int off = 16; off > 0; off >>= 1) dot += __shfl_xor_sync(0xffffffffu, dot, off);
    if (lane == 0) {
        float cosv = fminf(fmaxf(dot * g_winv[lab], -1.f), 1.f);
        float sinv = sqrtf(1.f - cosv * cosv + 1e-5f);
        float cm = cosv * COS_M - sinv * SIN_M;
        float tgt = (cosv > MIN_COS) ? cm : (cosv - sinv * MARG);
        g_cos_t[n] = cosv;
        g_tgt[n] = tgt;
    }
}

// ---------------------------------------------------------------------------
// Kernel 5: merge partials, fix up label column, NLL, mean. 1 block x 1024.
__global__ void k_final(float* __restrict__ out) {
    int t = threadIdx.x;
    float s = 0.f;
    // coalesced: [cb][n] layout
    for (int cb = 0; cb < NCB; cb++) s += g_partial[cb * NROWS + t];
    // replace plain label term with margin term
    float cosv = g_cos_t[t];
    float tgt = g_tgt[t];
    float s2 = s - expf(SCALE * cosv - SCALE) + expf(SCALE * tgt - SCALE);
    float nll = SCALE + logf(s2) - SCALE * tgt;   // logsumexp - target logit

    __shared__ float sred[1024];
    sred[t] = nll;
    __syncthreads();
    for (int off = 512; off > 0; off >>= 1) {
        if (t < off) sred[t] += sred[t + off];
        __syncthreads();
    }
    if (t == 0) out[0] = sred[0] * (1.0f / (float)NROWS);
}

// ---------------------------------------------------------------------------
extern "C" void kernel_launch(void* const* d_in, const int* in_sizes, int n_in,
                              void* d_out, int out_size) {
    const float* feats = (const float*)d_in[0];
    const float* w = (const float*)d_in[1];
    const int* labels = (const int*)d_in[2];
    float* out = (float*)d_out;

    k_norm_feats<<<NROWS, 128>>>(feats);
    k_winv<<<(NCLS + 7) / 8, 256>>>(w);
    k_main<<<dim3(8, NCB), 256>>>(w);
    k_label<<<NROWS / 8, 256>>>(w, labels);
    k_final<<<1, 1024>>>(out);
}

// round 5
// speedup vs baseline: 3.0437x; 3.0418x over previous
#include <cuda_runtime.h>
#include <math.h>
#include <stdint.h>

// ---------------- Problem constants ----------------
#define NROWS 1024
#define NCLS  100000
#define DIM   512
#define TILE_M 128
#define TILE_N 256
#define NCB   391            // ceil(100000/256)
#define NKC   16             // 512/32 k-chunks
#define KC    32
#define SCALE 64.0f
#define MARG  0.5f
#define COS_M 0.87758256189037271611f
#define SIN_M 0.47942553860420300027f
#define MIN_COS (-0.87758256189037271611f)

// smem strides (in floats): 36 => fragment LDS bank = (4*(lane/4)+lane%4)%32, conflict-free
#define STR 36
#define A_WORDS (TILE_M * STR)   // 4608
#define B_WORDS (TILE_N * STR)   // 9216

// ---------------- Scratch (device globals) ----------------
__device__ float g_fn[NROWS * DIM];          // normalized + tf32-rounded feats
__device__ float g_winv[NCLS + 256];
__device__ float g_partial[NCB * NROWS];
__device__ float g_cos_t[NROWS];
__device__ float g_tgt[NROWS];

// ---------------- helpers ----------------
__device__ __forceinline__ uint32_t smem_u32(const void* p) {
    uint32_t a;
    asm("{ .reg .u64 t; cvta.to.shared.u64 t, %1; cvt.u32.u64 %0, t; }" : "=r"(a) : "l"(p));
    return a;
}
__device__ __forceinline__ void cp16(uint32_t dst, const void* src) {
    asm volatile("cp.async.cg.shared.global [%0], [%1], 16;" :: "r"(dst), "l"(src) : "memory");
}
__device__ __forceinline__ uint32_t cvt_tf32(float f) {
    uint32_t r;
    asm("cvt.rna.tf32.f32 %0, %1;" : "=r"(r) : "f"(f));
    return r;
}
__device__ __forceinline__ float round_tf32(float f) {
    uint32_t r = cvt_tf32(f);
    return __uint_as_float(r);
}
__device__ __forceinline__ void mma_tf32_16x8x8(float* d, const uint32_t* a, const uint32_t* b) {
    asm volatile(
        "mma.sync.aligned.m16n8k8.row.col.f32.tf32.tf32.f32 "
        "{%0,%1,%2,%3}, {%4,%5,%6,%7}, {%8,%9}, {%0,%1,%2,%3};"
        : "+f"(d[0]), "+f"(d[1]), "+f"(d[2]), "+f"(d[3])
        : "r"(a[0]), "r"(a[1]), "r"(a[2]), "r"(a[3]), "r"(b[0]), "r"(b[1]));
}

// ---------------------------------------------------------------------------
// Kernel 1: normalize feats rows (+ tf32 rounding). grid=1024 x 128.
__global__ void k_norm_feats(const float* __restrict__ feats) {
    int row = blockIdx.x;
    int t = threadIdx.x;
    const float* x = feats + row * DIM;
    float v[4];
    float ss = 0.f;
#pragma unroll
    for (int i = 0; i < 4; i++) { v[i] = x[t + i * 128]; ss += v[i] * v[i]; }
#pragma unroll
    for (int off = 16; off > 0; off >>= 1) ss += __shfl_xor_sync(0xffffffffu, ss, off);
    __shared__ float sred[4];
    __shared__ float srinv;
    int lane = t & 31, wp = t >> 5;
    if (lane == 0) sred[wp] = ss;
    __syncthreads();
    if (t == 0) {
        float tot = sred[0] + sred[1] + sred[2] + sred[3];
        srinv = 1.f / fmaxf(sqrtf(tot), 1e-12f);
    }
    __syncthreads();
    float rinv = srinv;
#pragma unroll
    for (int i = 0; i < 4; i++)
        g_fn[row * DIM + t + i * 128] = round_tf32(v[i] * rinv);
}

// ---------------------------------------------------------------------------
// Kernel 2: inverse norms of W rows. One warp per row.
__global__ void k_winv(const float* __restrict__ w) {
    int wp = threadIdx.x >> 5, lane = threadIdx.x & 31;
    int row = blockIdx.x * 8 + wp;
    if (row >= NCLS) return;
    const float* x = w + (size_t)row * DIM;
    float ss = 0.f;
#pragma unroll
    for (int i = 0; i < 16; i++) { float v = x[lane + i * 32]; ss += v * v; }
#pragma unroll
    for (int off = 16; off > 0; off >>= 1) ss += __shfl_xor_sync(0xffffffffu, ss, off);
    if (lane == 0) g_winv[row] = 1.f / fmaxf(sqrtf(ss), 1e-12f);
}

// ---------------------------------------------------------------------------
// Kernel 3: tf32 mma.sync GEMM 128x256 per CTA + fused exp/row-sum.
// 256 threads = 8 warps (2M x 4N), warp tile 64x64 (m16n8k8 grid 4x8).
// Double-buffered cp.async, K in 32-chunks.
__global__ void __launch_bounds__(256, 1)
k_main_mma(const float* __restrict__ w) {
    extern __shared__ float sm[];
    float* s_winv = sm;                    // 256
    float* s_red  = sm + 256;              // 4 * 128
    float* sA0 = sm + 768;
    float* sA1 = sA0 + A_WORDS;
    float* sB0 = sA1 + A_WORDS;
    float* sB1 = sB0 + B_WORDS;

    const int tid = threadIdx.x;
    const int wid = tid >> 5;
    const int lane = tid & 31;
    const int l4 = lane >> 2;      // 0..7
    const int lm = lane & 3;       // 0..3
    const int warpM = (wid & 1) * 64;
    const int warpN = (wid >> 1) * 64;
    const int rowBase = blockIdx.x * TILE_M;
    const int colBase = blockIdx.y * TILE_N;

    const uint32_t aAddr[2] = { smem_u32(sA0), smem_u32(sA1) };
    const uint32_t bAddr[2] = { smem_u32(sB0), smem_u32(sB1) };
    const float* sA[2] = { sA0, sA1 };
    const float* sB[2] = { sB0, sB1 };

    // winv tile
#pragma unroll 1
    for (int i = tid; i < TILE_N; i += 256) {
        int c = colBase + i;
        s_winv[i] = (c < NCLS) ? g_winv[c] : 0.f;
    }

    float acc[4][8][4];
#pragma unroll
    for (int i = 0; i < 4; i++)
#pragma unroll
        for (int j = 0; j < 8; j++)
#pragma unroll
            for (int e = 0; e < 4; e++) acc[i][j][e] = 0.f;

    // chunk loader (all 256 threads)
    auto load_chunk = [&](int c, int s) {
        const int kt = c * KC;
        const uint32_t dA = aAddr[s], dB = bAddr[s];
#pragma unroll
        for (int i = 0; i < 4; i++) {
            int idx = tid + i * 256;
            int r = idx >> 3, kq = idx & 7;
            cp16(dA + (uint32_t)(r * STR + kq * 4) * 4,
                 &g_fn[(rowBase + r) * DIM + kt + kq * 4]);
        }
#pragma unroll
        for (int i = 0; i < 8; i++) {
            int idx = tid + i * 256;
            int r = idx >> 3, kq = idx & 7;
            int col = colBase + r;
            if (col >= NCLS) col = NCLS - 1;   // clamped; masked in epilogue
            cp16(dB + (uint32_t)(r * STR + kq * 4) * 4,
                 &w[(size_t)col * DIM + kt + kq * 4]);
        }
        asm volatile("cp.async.commit_group;" ::: "memory");
    };

    load_chunk(0, 0);

#pragma unroll 1
    for (int c = 0; c < NKC; c++) {
        const int s = c & 1;
        if (c + 1 < NKC) {
            load_chunk(c + 1, s ^ 1);
            asm volatile("cp.async.wait_group 1;" ::: "memory");
        } else {
            asm volatile("cp.async.wait_group 0;" ::: "memory");
        }
        __syncthreads();

        const float* A = sA[s];
        const float* B = sB[s];
#pragma unroll
        for (int ks = 0; ks < 4; ks++) {
            uint32_t af[4][4];
            uint32_t bf[8][2];
#pragma unroll
            for (int tm = 0; tm < 4; tm++) {
                const float* base = A + (warpM + tm * 16 + l4) * STR + ks * 8 + lm;
                af[tm][0] = __float_as_uint(base[0]);
                af[tm][1] = __float_as_uint(base[8 * STR]);
                af[tm][2] = __float_as_uint(base[4]);
                af[tm][3] = __float_as_uint(base[8 * STR + 4]);
            }
#pragma unroll
            for (int tn = 0; tn < 8; tn++) {
                const float* base = B + (warpN + tn * 8 + l4) * STR + ks * 8 + lm;
                bf[tn][0] = cvt_tf32(base[0]);
                bf[tn][1] = cvt_tf32(base[4]);
            }
#pragma unroll
            for (int tm = 0; tm < 4; tm++)
#pragma unroll
                for (int tn = 0; tn < 8; tn++)
                    mma_tf32_16x8x8(acc[tm][tn], af[tm], bf[tn]);
        }
        __syncthreads();
    }

    // ---------------- epilogue: cos -> clamp -> exp -> row sums ----------------
    float rs[4][2];
#pragma unroll
    for (int tm = 0; tm < 4; tm++) { rs[tm][0] = 0.f; rs[tm][1] = 0.f; }

#pragma unroll
    for (int tn = 0; tn < 8; tn++) {
        int lc = warpN + tn * 8 + 2 * lm;
        float w0 = s_winv[lc];
        float w1 = s_winv[lc + 1];
        float m0 = (colBase + lc < NCLS) ? 1.f : 0.f;
        float m1 = (colBase + lc + 1 < NCLS) ? 1.f : 0.f;
#pragma unroll
        for (int tm = 0; tm < 4; tm++) {
            float c0 = fminf(fmaxf(acc[tm][tn][0] * w0, -1.f), 1.f);
            float c1 = fminf(fmaxf(acc[tm][tn][1] * w1, -1.f), 1.f);
            float c2 = fminf(fmaxf(acc[tm][tn][2] * w0, -1.f), 1.f);
            float c3 = fminf(fmaxf(acc[tm][tn][3] * w1, -1.f), 1.f);
            rs[tm][0] += m0 * __expf(c0 * SCALE - SCALE) + m1 * __expf(c1 * SCALE - SCALE);
            rs[tm][1] += m0 * __expf(c2 * SCALE - SCALE) + m1 * __expf(c3 * SCALE - SCALE);
        }
    }
    // quad reduce: lanes lm=0 hold full 64-col sums
#pragma unroll
    for (int tm = 0; tm < 4; tm++)
#pragma unroll
        for (int h = 0; h < 2; h++) {
            float v = rs[tm][h];
            v += __shfl_xor_sync(0xffffffffu, v, 1);
            v += __shfl_xor_sync(0xffffffffu, v, 2);
            rs[tm][h] = v;
        }
    if (lm == 0) {
        int wn = wid >> 1;
#pragma unroll
        for (int tm = 0; tm < 4; tm++) {
            int r0 = warpM + tm * 16 + l4;
            s_red[wn * 128 + r0] = rs[tm][0];
            s_red[wn * 128 + r0 + 8] = rs[tm][1];
        }
    }
    __syncthreads();
    if (tid < 128) {
        float s = s_red[tid] + s_red[128 + tid] + s_red[256 + tid] + s_red[384 + tid];
        g_partial[blockIdx.y * NROWS + rowBase + tid] = s;
    }
}

// ---------------------------------------------------------------------------
// Kernel 4: label-column cos + margin target (fp32).
__global__ void k_label(const float* __restrict__ w, const int* __restrict__ labels) {
    int wp = threadIdx.x >> 5, lane = threadIdx.x & 31;
    int n = blockIdx.x * 8 + wp;
    if (n >= NROWS) return;
    int lab = labels[n];
    const float* fr = g_fn + n * DIM;
    const float* wr = w + (size_t)lab * DIM;
    float dot = 0.f;
#pragma unroll
    for (int i = 0; i < 16; i++) dot += fr[lane + i * 32] * wr[lane + i * 32];
#pragma unroll
    for (int off = 16; off > 0; off >>= 1) dot += __shfl_xor_sync(0xffffffffu, dot, off);
    if (lane == 0) {
        float cosv = fminf(fmaxf(dot * g_winv[lab], -1.f), 1.f);
        float sinv = sqrtf(1.f - cosv * cosv + 1e-5f);
        float cm = cosv * COS_M - sinv * SIN_M;
        float tgt = (cosv > MIN_COS) ? cm : (cosv - sinv * MARG);
        g_cos_t[n] = cosv;
        g_tgt[n] = tgt;
    }
}

// ---------------------------------------------------------------------------
// Kernel 5: merge partials, label fix-up, NLL, mean.
__global__ void k_final(float* __restrict__ out) {
    int t = threadIdx.x;
    float s = 0.f;
    for (int cb = 0; cb < NCB; cb++) s += g_partial[cb * NROWS + t];
    float cosv = g_cos_t[t];
    float tgt = g_tgt[t];
    float s2 = s - expf(SCALE * cosv - SCALE) + expf(SCALE * tgt - SCALE);
    float nll = SCALE + logf(s2) - SCALE * tgt;

    __shared__ float sred[1024];
    sred[t] = nll;
    __syncthreads();
    for (int off = 512; off > 0; off >>= 1) {
        if (t < off) sred[t] += sred[t + off];
        __syncthreads();
    }
    if (t == 0) out[0] = sred[0] * (1.0f / (float)NROWS);
}

// ---------------------------------------------------------------------------
#define SMEM_BYTES ((768 + 2 * A_WORDS + 2 * B_WORDS) * 4)

extern "C" void kernel_launch(void* const* d_in, const int* in_sizes, int n_in,
                              void* d_out, int out_size) {
    const float* feats = (const float*)d_in[0];
    const float* w = (const float*)d_in[1];
    const int* labels = (const int*)d_in[2];
    float* out = (float*)d_out;

    cudaFuncSetAttribute(k_main_mma, cudaFuncAttributeMaxDynamicSharedMemorySize, SMEM_BYTES);

    k_norm_feats<<<NROWS, 128>>>(feats);
    k_winv<<<(NCLS + 7) / 8, 256>>>(w);
    k_main_mma<<<dim3(NROWS / TILE_M, NCB), 256, SMEM_BYTES>>>(w);
    k_label<<<NROWS / 8, 256>>>(w, labels);
    k_final<<<1, 1024>>>(out);
}

// round 6
// speedup vs baseline: 4.5966x; 1.5102x over previous
#include <cuda_runtime.h>
#include <cuda_bf16.h>
#include <math.h>
#include <stdint.h>

// ---------------- Problem constants ----------------
#define NROWS 1024
#define NCLS  100000
#define DIM   512
#define TILE_M 128
#define TILE_N 256
#define NCB   391            // ceil(100000/256)
#define NKC   16             // 512/32 k-chunks
#define KC    32
#define SCALE 64.0f
#define MARG  0.5f
#define COS_M 0.87758256189037271611f
#define SIN_M 0.47942553860420300027f
#define MIN_COS (-0.87758256189037271611f)

// bf16 smem row stride (in bf16 elems): 40 => 80B rows, conflict-free frags
#define STRH 40

// ---------------- Scratch (device globals) ----------------
__device__ float g_fn[NROWS * DIM];                 // normalized feats fp32 (k_label)
__device__ __nv_bfloat16 g_fnb[NROWS * DIM];        // normalized feats bf16 (GEMM A)
__device__ __nv_bfloat16 g_wnb[(size_t)NCLS * DIM]; // normalized W bf16 (GEMM B)
__device__ float g_winv[NCLS];
__device__ float g_partial[NCB * NROWS];
__device__ float g_cosl[NROWS];                     // approx label cos (from GEMM)
__device__ float g_tgt[NROWS];                      // exact margin target

// ---------------- helpers ----------------
__device__ __forceinline__ uint32_t smem_u32(const void* p) {
    uint32_t a;
    asm("{ .reg .u64 t; cvta.to.shared.u64 t, %1; cvt.u32.u64 %0, t; }" : "=r"(a) : "l"(p));
    return a;
}
__device__ __forceinline__ void cp16(uint32_t dst, const void* src) {
    asm volatile("cp.async.cg.shared.global [%0], [%1], 16;" :: "r"(dst), "l"(src) : "memory");
}
__device__ __forceinline__ void mma_bf16(float* d, const uint32_t* a, const uint32_t* b) {
    asm volatile(
        "mma.sync.aligned.m16n8k16.row.col.f32.bf16.bf16.f32 "
        "{%0,%1,%2,%3}, {%4,%5,%6,%7}, {%8,%9}, {%0,%1,%2,%3};"
        : "+f"(d[0]), "+f"(d[1]), "+f"(d[2]), "+f"(d[3])
        : "r"(a[0]), "r"(a[1]), "r"(a[2]), "r"(a[3]), "r"(b[0]), "r"(b[1]));
}

// ---------------------------------------------------------------------------
// Kernel 1: normalize feats rows -> fp32 + bf16. grid=1024 x 128.
__global__ void k_norm_feats(const float* __restrict__ feats) {
    int row = blockIdx.x;
    int t = threadIdx.x;
    const float* x = feats + row * DIM;
    float v[4];
    float ss = 0.f;
#pragma unroll
    for (int i = 0; i < 4; i++) { v[i] = x[t + i * 128]; ss += v[i] * v[i]; }
#pragma unroll
    for (int off = 16; off > 0; off >>= 1) ss += __shfl_xor_sync(0xffffffffu, ss, off);
    __shared__ float sred[4];
    __shared__ float srinv;
    int lane = t & 31, wp = t >> 5;
    if (lane == 0) sred[wp] = ss;
    __syncthreads();
    if (t == 0) {
        float tot = sred[0] + sred[1] + sred[2] + sred[3];
        srinv = 1.f / fmaxf(sqrtf(tot), 1e-12f);
    }
    __syncthreads();
    float rinv = srinv;
#pragma unroll
    for (int i = 0; i < 4; i++) {
        float y = v[i] * rinv;
        g_fn[row * DIM + t + i * 128] = y;
        g_fnb[row * DIM + t + i * 128] = __float2bfloat16(y);
    }
}

// ---------------------------------------------------------------------------
// Kernel 2: normalize W rows -> bf16 (+ winv for exact label path).
// One warp per row, float2 lanes for coalescing. grid=12500 x 256.
__global__ void k_wnorm(const float* __restrict__ w) {
    int wp = threadIdx.x >> 5, lane = threadIdx.x & 31;
    int row = blockIdx.x * 8 + wp;
    if (row >= NCLS) return;
    const float2* x = (const float2*)(w + (size_t)row * DIM);
    float2 v[8];
    float ss = 0.f;
#pragma unroll
    for (int i = 0; i < 8; i++) {
        v[i] = x[lane + i * 32];
        ss += v[i].x * v[i].x + v[i].y * v[i].y;
    }
#pragma unroll
    for (int off = 16; off > 0; off >>= 1) ss += __shfl_xor_sync(0xffffffffu, ss, off);
    float rinv = 1.f / fmaxf(sqrtf(ss), 1e-12f);
    __nv_bfloat162* dst = (__nv_bfloat162*)(g_wnb + (size_t)row * DIM);
#pragma unroll
    for (int i = 0; i < 8; i++)
        dst[lane + i * 32] = __float22bfloat162_rn(make_float2(v[i].x * rinv, v[i].y * rinv));
    if (lane == 0) g_winv[row] = rinv;
}

// ---------------------------------------------------------------------------
// Kernel 3: bf16 mma.sync GEMM 128x256 per CTA + fused exp/row-sum + label tap.
// 256 threads = 8 warps (2M x 4N), warp tile 64x64 (m16n8k16 grid 4x8).
#define OFF_RED 0        // 512 floats (2048 B)
#define OFF_LAB 2048     // 128 ints (512 B)
#define OFF_A0  2560     // 128 x 40 bf16 = 10240 B
#define OFF_B0  12800    // 256 x 40 bf16 = 20480 B
#define OFF_A1  33280
#define OFF_B1  43520
#define SMEM_BYTES 64000

__global__ void __launch_bounds__(256, 1)
k_main_mma(const int* __restrict__ labels) {
    extern __shared__ char sm[];
    const uint32_t sb = smem_u32(sm);
    float* s_red = (float*)(sm + OFF_RED);
    int* s_lab = (int*)(sm + OFF_LAB);

    const int tid = threadIdx.x;
    const int wid = tid >> 5;
    const int lane = tid & 31;
    const int l4 = lane >> 2;      // 0..7
    const int lm = lane & 3;       // 0..3
    const int warpM = (wid & 1) * 64;
    const int warpN = (wid >> 1) * 64;
    const int rowBase = blockIdx.x * TILE_M;
    const int colBase = blockIdx.y * TILE_N;

    if (tid < TILE_M) s_lab[tid] = labels[rowBase + tid];

    float acc[4][8][4];
#pragma unroll
    for (int i = 0; i < 4; i++)
#pragma unroll
        for (int j = 0; j < 8; j++)
#pragma unroll
            for (int e = 0; e < 4; e++) acc[i][j][e] = 0.f;

    const uint32_t aOff[2] = { sb + OFF_A0, sb + OFF_A1 };
    const uint32_t bOff[2] = { sb + OFF_B0, sb + OFF_B1 };
    const __nv_bfloat16* sA[2] = { (const __nv_bfloat16*)(sm + OFF_A0),
                                   (const __nv_bfloat16*)(sm + OFF_A1) };
    const __nv_bfloat16* sB[2] = { (const __nv_bfloat16*)(sm + OFF_B0),
                                   (const __nv_bfloat16*)(sm + OFF_B1) };

    auto load_chunk = [&](int c, int s) {
        const int kt = c * KC;
        // A: 128 rows x 32 bf16 (64 B/row) = 512 cp16
#pragma unroll
        for (int i = 0; i < 2; i++) {
            int idx = tid + i * 256;
            int r = idx >> 2, kq = idx & 3;
            cp16(aOff[s] + (uint32_t)(r * 80 + kq * 16),
                 &g_fnb[(rowBase + r) * DIM + kt + kq * 8]);
        }
        // B: 256 class rows x 32 bf16 = 1024 cp16
#pragma unroll
        for (int i = 0; i < 4; i++) {
            int idx = tid + i * 256;
            int r = idx >> 2, kq = idx & 3;
            int col = colBase + r;
            if (col >= NCLS) col = NCLS - 1;   // masked in epilogue
            cp16(bOff[s] + (uint32_t)(r * 80 + kq * 16),
                 &g_wnb[(size_t)col * DIM + kt + kq * 8]);
        }
        asm volatile("cp.async.commit_group;" ::: "memory");
    };

    load_chunk(0, 0);

#pragma unroll 1
    for (int c = 0; c < NKC; c++) {
        const int s = c & 1;
        if (c + 1 < NKC) {
            load_chunk(c + 1, s ^ 1);
            asm volatile("cp.async.wait_group 1;" ::: "memory");
        } else {
            asm volatile("cp.async.wait_group 0;" ::: "memory");
        }
        __syncthreads();

        const __nv_bfloat16* A = sA[s];
        const __nv_bfloat16* B = sB[s];
#pragma unroll
        for (int ks = 0; ks < 2; ks++) {
            uint32_t af[4][4];
            uint32_t bf[8][2];
#pragma unroll
            for (int tm = 0; tm < 4; tm++) {
                const __nv_bfloat16* p0 = A + (warpM + tm * 16 + l4) * STRH + ks * 16 + 2 * lm;
                const __nv_bfloat16* p1 = p0 + 8 * STRH;
                af[tm][0] = *(const uint32_t*)p0;
                af[tm][1] = *(const uint32_t*)p1;
                af[tm][2] = *(const uint32_t*)(p0 + 8);
                af[tm][3] = *(const uint32_t*)(p1 + 8);
            }
#pragma unroll
            for (int tn = 0; tn < 8; tn++) {
                const __nv_bfloat16* p = B + (warpN + tn * 8 + l4) * STRH + ks * 16 + 2 * lm;
                bf[tn][0] = *(const uint32_t*)p;
                bf[tn][1] = *(const uint32_t*)(p + 8);
            }
#pragma unroll
            for (int tm = 0; tm < 4; tm++)
#pragma unroll
                for (int tn = 0; tn < 8; tn++)
                    mma_bf16(acc[tm][tn], af[tm], bf[tn]);
        }
        __syncthreads();
    }

    // ---------------- epilogue: clamp -> exp -> row sums (+ label tap) --------
    float rs[4][2];
#pragma unroll
    for (int tm = 0; tm < 4; tm++) { rs[tm][0] = 0.f; rs[tm][1] = 0.f; }

#pragma unroll
    for (int tn = 0; tn < 8; tn++) {
        int lc = warpN + tn * 8 + 2 * lm;      // local col of elems 0/2
        int gc0 = colBase + lc;
        int gc1 = gc0 + 1;
        float m0 = (gc0 < NCLS) ? 1.f : 0.f;
        float m1 = (gc1 < NCLS) ? 1.f : 0.f;
#pragma unroll
        for (int tm = 0; tm < 4; tm++) {
            int r0 = warpM + tm * 16 + l4;     // local row of elems 0/1
            int r1 = r0 + 8;                   // local row of elems 2/3
            float c0 = fminf(fmaxf(acc[tm][tn][0], -1.f), 1.f);
            float c1 = fminf(fmaxf(acc[tm][tn][1], -1.f), 1.f);
            float c2 = fminf(fmaxf(acc[tm][tn][2], -1.f), 1.f);
            float c3 = fminf(fmaxf(acc[tm][tn][3], -1.f), 1.f);
            // label tap: record the GEMM's own label-column cos (exact cancel later)
            if (gc0 == s_lab[r0]) g_cosl[rowBase + r0] = c0;
            if (gc1 == s_lab[r0]) g_cosl[rowBase + r0] = c1;
            if (gc0 == s_lab[r1]) g_cosl[rowBase + r1] = c2;
            if (gc1 == s_lab[r1]) g_cosl[rowBase + r1] = c3;
            rs[tm][0] += m0 * __expf(c0 * SCALE - SCALE) + m1 * __expf(c1 * SCALE - SCALE);
            rs[tm][1] += m0 * __expf(c2 * SCALE - SCALE) + m1 * __expf(c3 * SCALE - SCALE);
        }
    }
    // quad reduce: lanes lm=0 hold full 64-col sums
#pragma unroll
    for (int tm = 0; tm < 4; tm++)
#pragma unroll
        for (int h = 0; h < 2; h++) {
            float v = rs[tm][h];
            v += __shfl_xor_sync(0xffffffffu, v, 1);
            v += __shfl_xor_sync(0xffffffffu, v, 2);
            rs[tm][h] = v;
        }
    if (lm == 0) {
        int wn = wid >> 1;
#pragma unroll
        for (int tm = 0; tm < 4; tm++) {
            int r0 = warpM + tm * 16 + l4;
            s_red[wn * 128 + r0] = rs[tm][0];
            s_red[wn * 128 + r0 + 8] = rs[tm][1];
        }
    }
    __syncthreads();
    if (tid < 128) {
        float s = s_red[tid] + s_red[128 + tid] + s_red[256 + tid] + s_red[384 + tid];
        g_partial[blockIdx.y * NROWS + rowBase + tid] = s;
    }
}

// ---------------------------------------------------------------------------
// Kernel 4: exact fp32 label cos -> margin target.
__global__ void k_label(const float* __restrict__ w, const int* __restrict__ labels) {
    int wp = threadIdx.x >> 5, lane = threadIdx.x & 31;
    int n = blockIdx.x * 8 + wp;
    if (n >= NROWS) return;
    int lab = labels[n];
    const float* fr = g_fn + n * DIM;
    const float* wr = w + (size_t)lab * DIM;
    float dot = 0.f;
#pragma unroll
    for (int i = 0; i < 16; i++) dot += fr[lane + i * 32] * wr[lane + i * 32];
#pragma unroll
    for (int off = 16; off > 0; off >>= 1) dot += __shfl_xor_sync(0xffffffffu, dot, off);
    if (lane == 0) {
        float cosv = fminf(fmaxf(dot * g_winv[lab], -1.f), 1.f);
        float sinv = sqrtf(1.f - cosv * cosv + 1e-5f);
        float cm = cosv * COS_M - sinv * SIN_M;
        g_tgt[n] = (cosv > MIN_COS) ? cm : (cosv - sinv * MARG);
    }
}

// ---------------------------------------------------------------------------
// Kernel 5: merge partials, exact label swap, NLL, mean.
__global__ void k_final(float* __restrict__ out) {
    int t = threadIdx.x;
    float s = 0.f;
    for (int cb = 0; cb < NCB; cb++) s += g_partial[cb * NROWS + t];
    float cosl = g_cosl[t];                      // approx term actually inside s
    float tgt = g_tgt[t];                        // exact margin target
    float s2 = s - expf(SCALE * cosl - SCALE) + expf(SCALE * tgt - SCALE);
    float nll = SCALE + logf(s2) - SCALE * tgt;

    __shared__ float sred[1024];
    sred[t] = nll;
    __syncthreads();
    for (int off = 512; off > 0; off >>= 1) {
        if (t < off) sred[t] += sred[t + off];
        __syncthreads();
    }
    if (t == 0) out[0] = sred[0] * (1.0f / (float)NROWS);
}

// ---------------------------------------------------------------------------
extern "C" void kernel_launch(void* const* d_in, const int* in_sizes, int n_in,
                              void* d_out, int out_size) {
    const float* feats = (const float*)d_in[0];
    const float* w = (const float*)d_in[1];
    const int* labels = (const int*)d_in[2];
    float* out = (float*)d_out;

    cudaFuncSetAttribute(k_main_mma, cudaFuncAttributeMaxDynamicSharedMemorySize, SMEM_BYTES);

    k_norm_feats<<<NROWS, 128>>>(feats);
    k_wnorm<<<(NCLS + 7) / 8, 256>>>(w);
    k_main_mma<<<dim3(NROWS / TILE_M, NCB), 256, SMEM_BYTES>>>(labels);
    k_label<<<NROWS / 8, 256>>>(w, labels);
    k_final<<<1, 1024>>>(out);
}

// round 7
// speedup vs baseline: 5.2651x; 1.1454x over previous
#include <cuda_runtime.h>
#include <math.h>
#include <stdint.h>

// ---------------- Problem constants ----------------
#define NROWS 1024
#define NCLS  100000
#define DIM   512
#define NSLOTS 444           // 296 (TN=8) + 148 (TN=6) partial slots
#define SCALE 64.0f
#define MARG  0.5f
#define COS_M 0.87758256189037271611f
#define SIN_M 0.47942553860420300027f
#define MIN_COS (-0.87758256189037271611f)
#define FP8_SCALE 16.0f      // power of 2: exact; acc = 256 * cos

// ---------------- Scratch (device globals) ----------------
__device__ float g_fn[NROWS * DIM];                   // normalized feats fp32 (label path)
__device__ unsigned short g_fnb8[NROWS * DIM / 2];    // feats e4m3x2 (x16)
__device__ unsigned short g_wnb8[(size_t)NCLS * DIM / 2]; // W normalized e4m3x2 (x16)
__device__ float g_winv[NCLS];
__device__ float g_partial[NSLOTS * NROWS];
__device__ float g_cosl[NROWS];                       // label LOGIT actually summed
__device__ float g_tgt[NROWS];                        // exact margin target

// ---------------- helpers ----------------
__device__ __forceinline__ uint32_t smem_u32(const void* p) {
    uint32_t a;
    asm("{ .reg .u64 t; cvta.to.shared.u64 t, %1; cvt.u32.u64 %0, t; }" : "=r"(a) : "l"(p));
    return a;
}
__device__ __forceinline__ void cp16(uint32_t dst, const void* src) {
    asm volatile("cp.async.cg.shared.global [%0], [%1], 16;" :: "r"(dst), "l"(src) : "memory");
}
__device__ __forceinline__ unsigned short cvt_e4m3x2(float hi, float lo) {
    unsigned short r;
    asm("cvt.rn.satfinite.e4m3x2.f32 %0, %1, %2;" : "=h"(r) : "f"(hi), "f"(lo));
    return r;
}
__device__ __forceinline__ void mma_fp8(float* d, const uint32_t* a, const uint32_t* b) {
    asm volatile(
        "mma.sync.aligned.m16n8k32.row.col.f32.e4m3.e4m3.f32 "
        "{%0,%1,%2,%3}, {%4,%5,%6,%7}, {%8,%9}, {%0,%1,%2,%3};"
        : "+f"(d[0]), "+f"(d[1]), "+f"(d[2]), "+f"(d[3])
        : "r"(a[0]), "r"(a[1]), "r"(a[2]), "r"(a[3]), "r"(b[0]), "r"(b[1]));
}

// ---------------------------------------------------------------------------
// Kernel 1: normalize feats rows -> fp32 + e4m3(x16). grid=1024 x 128.
__global__ void k_norm_feats(const float* __restrict__ feats) {
    int row = blockIdx.x;
    int t = threadIdx.x;
    const float2* x = (const float2*)(feats + row * DIM);   // 256 float2
    float2 v[2];
    v[0] = x[t]; v[1] = x[t + 128];
    float ss = v[0].x * v[0].x + v[0].y * v[0].y + v[1].x * v[1].x + v[1].y * v[1].y;
#pragma unroll
    for (int off = 16; off > 0; off >>= 1) ss += __shfl_xor_sync(0xffffffffu, ss, off);
    __shared__ float sred[4];
    __shared__ float srinv;
    int lane = t & 31, wp = t >> 5;
    if (lane == 0) sred[wp] = ss;
    __syncthreads();
    if (t == 0) {
        float tot = sred[0] + sred[1] + sred[2] + sred[3];
        srinv = 1.f / fmaxf(sqrtf(tot), 1e-12f);
    }
    __syncthreads();
    float rinv = srinv;
#pragma unroll
    for (int i = 0; i < 2; i++) {
        int j = t + i * 128;
        float yx = v[i].x * rinv, yy = v[i].y * rinv;
        g_fn[row * DIM + 2 * j] = yx;
        g_fn[row * DIM + 2 * j + 1] = yy;
        g_fnb8[row * 256 + j] = cvt_e4m3x2(yy * FP8_SCALE, yx * FP8_SCALE);
    }
}

// ---------------------------------------------------------------------------
// Kernel 2: normalize W rows -> e4m3(x16) + winv. One warp per row.
__global__ void k_wnorm(const float* __restrict__ w) {
    int wp = threadIdx.x >> 5, lane = threadIdx.x & 31;
    int row = blockIdx.x * 8 + wp;
    if (row >= NCLS) return;
    const float2* x = (const float2*)(w + (size_t)row * DIM);
    float2 v[8];
    float ss = 0.f;
#pragma unroll
    for (int i = 0; i < 8; i++) {
        v[i] = x[lane + i * 32];
        ss += v[i].x * v[i].x + v[i].y * v[i].y;
    }
#pragma unroll
    for (int off = 16; off > 0; off >>= 1) ss += __shfl_xor_sync(0xffffffffu, ss, off);
    float rinv = 1.f / fmaxf(sqrtf(ss), 1e-12f);
    unsigned short* dst = g_wnb8 + (size_t)row * 256;
    float rs16 = rinv * FP8_SCALE;
#pragma unroll
    for (int i = 0; i < 8; i++)
        dst[lane + i * 32] = cvt_e4m3x2(v[i].y * rs16, v[i].x * rs16);
    if (lane == 0) g_winv[row] = rinv;
}

// ---------------------------------------------------------------------------
// Kernel 3: fp8 mma GEMM, B-resident. CTA owns TN*32 cols, loops all 8 M-tiles.
// 256 threads = 8 warps (2M x 4N); warp tile 64 x (TN*8); m16n8k32.
// smem: [0,2048) s_red, [2048,2560) s_lab, [2560,8704) A0, [8704,14848) A1,
//       [14848, +TN*32*528) B resident (528B row stride: conflict-free frags)
#define OFF_A0 2560
#define OFF_A1 8704
#define OFF_B  14848

template <int TN>
__global__ void __launch_bounds__(256, 1)
k_main_fp8(const int* __restrict__ labels, int colBase0, int slotBase) {
    extern __shared__ char sm[];
    constexpr int TILE_NN = TN * 32;
    float* s_red = (float*)sm;
    int* s_lab = (int*)(sm + 2048);
    const uint32_t sb = smem_u32(sm);
    const uint32_t aBuf[2] = { sb + OFF_A0, sb + OFF_A1 };
    const char* sAc[2] = { sm + OFF_A0, sm + OFF_A1 };
    const char* sBc = sm + OFF_B;

    const int tid = threadIdx.x;
    const int wid = tid >> 5, lane = tid & 31;
    const int l4 = lane >> 2, lm = lane & 3;
    const int warpM = (wid & 1) * 64;
    const int warpN = (wid >> 1) * (TN * 8);
    const int colBase = colBase0 + blockIdx.x * TILE_NN;
    const int slot = slotBase + blockIdx.x;

    // ---- B resident load: TILE_NN rows x 512 B, row stride 528 ----
#pragma unroll
    for (int i = 0; i < TN * 4; i++) {
        int idx = tid + i * 256;
        int r = idx >> 5, kq = idx & 31;
        int col = colBase + r;
        if (col >= NCLS) col = NCLS - 1;          // masked in epilogue
        cp16(sb + OFF_B + (uint32_t)(r * 528 + kq * 16),
             (const char*)g_wnb8 + (size_t)col * 512 + kq * 16);
    }
    asm volatile("cp.async.commit_group;" ::: "memory");

    // ---- A chunk loader: chunk g = mt*16 + kc covers rows mt*128.., K kc*32.. ----
    auto loadA = [&](int g, int buf) {
        int mt = g >> 4, kc = g & 15;
        int r = tid >> 1, kq = tid & 1;
        cp16(aBuf[buf] + (uint32_t)(r * 48 + kq * 16),
             (const char*)g_fnb8 + (size_t)(mt * 128 + r) * 512 + kc * 32 + kq * 16);
        asm volatile("cp.async.commit_group;" ::: "memory");
    };
    loadA(0, 0);

    float acc[4][TN][4];
#pragma unroll
    for (int i = 0; i < 4; i++)
#pragma unroll
        for (int j = 0; j < TN; j++)
#pragma unroll
            for (int e = 0; e < 4; e++) acc[i][j][e] = 0.f;

#pragma unroll 1
    for (int g = 0; g < 128; g++) {
        if (g + 1 < 128) {
            loadA(g + 1, (g + 1) & 1);
            asm volatile("cp.async.wait_group 1;" ::: "memory");
        } else {
            asm volatile("cp.async.wait_group 0;" ::: "memory");
        }
        __syncthreads();
        if ((g & 15) == 0 && tid < 128) s_lab[tid] = labels[(g >> 4) * 128 + tid];

        const char* A = sAc[g & 1];
        const int kOff = (g & 15) * 32;
        uint32_t af[4][4], bf[TN][2];
#pragma unroll
        for (int tm = 0; tm < 4; tm++) {
            const char* p = A + (warpM + tm * 16 + l4) * 48 + lm * 4;
            af[tm][0] = *(const uint32_t*)p;
            af[tm][1] = *(const uint32_t*)(p + 8 * 48);
            af[tm][2] = *(const uint32_t*)(p + 16);
            af[tm][3] = *(const uint32_t*)(p + 8 * 48 + 16);
        }
#pragma unroll
        for (int tn = 0; tn < TN; tn++) {
            const char* p = sBc + (warpN + tn * 8 + l4) * 528 + kOff + lm * 4;
            bf[tn][0] = *(const uint32_t*)p;
            bf[tn][1] = *(const uint32_t*)(p + 16);
        }
#pragma unroll
        for (int tm = 0; tm < 4; tm++)
#pragma unroll
            for (int tn = 0; tn < TN; tn++)
                mma_fp8(acc[tm][tn], af[tm], bf[tn]);
        __syncthreads();

        // ---- per-M-tile epilogue ----
        if ((g & 15) == 15) {
            const int rowBase = (g >> 4) * 128;
            float rs[4][2];
#pragma unroll
            for (int tm = 0; tm < 4; tm++) { rs[tm][0] = 0.f; rs[tm][1] = 0.f; }
#pragma unroll
            for (int tn = 0; tn < TN; tn++) {
                int lc = warpN + tn * 8 + 2 * lm;
                int gc0 = colBase + lc, gc1 = gc0 + 1;
                float m0 = (gc0 < NCLS) ? 1.f : 0.f;
                float m1 = (gc1 < NCLS) ? 1.f : 0.f;
#pragma unroll
                for (int tm = 0; tm < 4; tm++) {
                    int r0 = warpM + tm * 16 + l4;
                    int r1 = r0 + 8;
                    // logit = 64 * cos = acc * (64/256); clamp to [-64, 64]
                    float c0 = fminf(fmaxf(acc[tm][tn][0] * 0.25f, -64.f), 64.f);
                    float c1 = fminf(fmaxf(acc[tm][tn][1] * 0.25f, -64.f), 64.f);
                    float c2 = fminf(fmaxf(acc[tm][tn][2] * 0.25f, -64.f), 64.f);
                    float c3 = fminf(fmaxf(acc[tm][tn][3] * 0.25f, -64.f), 64.f);
                    if (gc0 == s_lab[r0]) g_cosl[rowBase + r0] = c0;
                    if (gc1 == s_lab[r0]) g_cosl[rowBase + r0] = c1;
                    if (gc0 == s_lab[r1]) g_cosl[rowBase + r1] = c2;
                    if (gc1 == s_lab[r1]) g_cosl[rowBase + r1] = c3;
                    rs[tm][0] += m0 * __expf(c0 - 64.f) + m1 * __expf(c1 - 64.f);
                    rs[tm][1] += m0 * __expf(c2 - 64.f) + m1 * __expf(c3 - 64.f);
                    acc[tm][tn][0] = 0.f; acc[tm][tn][1] = 0.f;
                    acc[tm][tn][2] = 0.f; acc[tm][tn][3] = 0.f;
                }
            }
#pragma unroll
            for (int tm = 0; tm < 4; tm++)
#pragma unroll
                for (int h = 0; h < 2; h++) {
                    float v = rs[tm][h];
                    v += __shfl_xor_sync(0xffffffffu, v, 1);
                    v += __shfl_xor_sync(0xffffffffu, v, 2);
                    rs[tm][h] = v;
                }
            if (lm == 0) {
                int wn = wid >> 1;
#pragma unroll
                for (int tm = 0; tm < 4; tm++) {
                    int r0 = warpM + tm * 16 + l4;
                    s_red[wn * 128 + r0] = rs[tm][0];
                    s_red[wn * 128 + r0 + 8] = rs[tm][1];
                }
            }
            __syncthreads();
            if (tid < 128) {
                float s = s_red[tid] + s_red[128 + tid] + s_red[256 + tid] + s_red[384 + tid];
                g_partial[slot * NROWS + rowBase + tid] = s;
            }
        }
    }
}

// ---------------------------------------------------------------------------
// Kernel 4: exact fp32 label cos -> margin target.
__global__ void k_label(const float* __restrict__ w, const int* __restrict__ labels) {
    int wp = threadIdx.x >> 5, lane = threadIdx.x & 31;
    int n = blockIdx.x * 8 + wp;
    if (n >= NROWS) return;
    int lab = labels[n];
    const float* fr = g_fn + n * DIM;
    const float* wr = w + (size_t)lab * DIM;
    float dot = 0.f;
#pragma unroll
    for (int i = 0; i < 16; i++) dot += fr[lane + i * 32] * wr[lane + i * 32];
#pragma unroll
    for (int off = 16; off > 0; off >>= 1) dot += __shfl_xor_sync(0xffffffffu, dot, off);
    if (lane == 0) {
        float cosv = fminf(fmaxf(dot * g_winv[lab], -1.f), 1.f);
        float sinv = sqrtf(1.f - cosv * cosv + 1e-5f);
        float cm = cosv * COS_M - sinv * SIN_M;
        g_tgt[n] = (cosv > MIN_COS) ? cm : (cosv - sinv * MARG);
    }
}

// ---------------------------------------------------------------------------
// Kernel 5: merge partials, exact label swap, NLL, mean.
__global__ void k_final(float* __restrict__ out) {
    int t = threadIdx.x;
    float s = 0.f;
    for (int cb = 0; cb < NSLOTS; cb++) s += g_partial[cb * NROWS + t];
    float cl = g_cosl[t];                        // label logit actually inside s
    float tgt = g_tgt[t];
    float s2 = s - expf(cl - 64.f) + expf(SCALE * tgt - 64.f);
    float nll = 64.f + logf(s2) - SCALE * tgt;

    __shared__ float sred[1024];
    sred[t] = nll;
    __syncthreads();
    for (int off = 512; off > 0; off >>= 1) {
        if (t < off) sred[t] += sred[t + off];
        __syncthreads();
    }
    if (t == 0) out[0] = sred[0] * (1.0f / (float)NROWS);
}

// ---------------------------------------------------------------------------
#define SMEM8 (OFF_B + 256 * 528)   // 150016
#define SMEM6 (OFF_B + 192 * 528)   // 116224

extern "C" void kernel_launch(void* const* d_in, const int* in_sizes, int n_in,
                              void* d_out, int out_size) {
    const float* feats = (const float*)d_in[0];
    const float* w = (const float*)d_in[1];
    const int* labels = (const int*)d_in[2];
    float* out = (float*)d_out;

    cudaFuncSetAttribute(k_main_fp8<8>, cudaFuncAttributeMaxDynamicSharedMemorySize, SMEM8);
    cudaFuncSetAttribute(k_main_fp8<6>, cudaFuncAttributeMaxDynamicSharedMemorySize, SMEM6);

    k_norm_feats<<<NROWS, 128>>>(feats);
    k_wnorm<<<(NCLS + 7) / 8, 256>>>(w);
    // 296 CTAs x 256 cols = 75776, then 148 CTAs x 192 cols = 28416 (>= 100000)
    k_main_fp8<8><<<296, 256, SMEM8>>>(labels, 0, 0);
    k_main_fp8<6><<<148, 256, SMEM6>>>(labels, 75776, 296);
    k_label<<<NROWS / 8, 256>>>(w, labels);
    k_final<<<1, 1024>>>(out);
}

// round 8
// speedup vs baseline: 6.1537x; 1.1688x over previous
#include <cuda_runtime.h>
#include <math.h>
#include <stdint.h>

// ---------------- Problem constants ----------------
#define NROWS 1024
#define NCLS  100000
#define DIM   512
#define NSLOTS 444           // 296 (TN=8) + 148 (TN=6) partial slots
#define SCALE 64.0f
#define MARG  0.5f
#define COS_M 0.87758256189037271611f
#define SIN_M 0.47942553860420300027f
#define MIN_COS (-0.87758256189037271611f)
#define FP8_SCALE 16.0f      // power of 2: exact; acc = 256 * cos

// Packed-B capacity: cover padded cols up to 104192 -> 13024 col8 groups
#define WB_USHORTS ((size_t)13024 * 2048)

// ---------------- Scratch (device globals) ----------------
__device__ float g_fn[NROWS * DIM];                 // normalized feats fp32 (label path)
__device__ unsigned short g_fnb8[NROWS * DIM / 2];  // feats e4m3 packed for LDS.128 frags
__device__ unsigned short g_wnb8[WB_USHORTS];       // W normalized e4m3 packed for LDS.64 frags (zero beyond NCLS)
__device__ float g_winv[NCLS];
__device__ float g_partial[NSLOTS * NROWS];
__device__ float g_cosl[NROWS];                     // label LOGIT actually summed
__device__ float g_tgt[NROWS];                      // exact margin target

// ---------------- helpers ----------------
__device__ __forceinline__ uint32_t smem_u32(const void* p) {
    uint32_t a;
    asm("{ .reg .u64 t; cvta.to.shared.u64 t, %1; cvt.u32.u64 %0, t; }" : "=r"(a) : "l"(p));
    return a;
}
__device__ __forceinline__ void cp16(uint32_t dst, const void* src) {
    asm volatile("cp.async.cg.shared.global [%0], [%1], 16;" :: "r"(dst), "l"(src) : "memory");
}
__device__ __forceinline__ unsigned short cvt_e4m3x2(float hi, float lo) {
    unsigned short r;
    asm("cvt.rn.satfinite.e4m3x2.f32 %0, %1, %2;" : "=h"(r) : "f"(hi), "f"(lo));
    return r;
}
__device__ __forceinline__ void mma_fp8(float* d, const uint32_t* a, const uint32_t* b) {
    asm volatile(
        "mma.sync.aligned.m16n8k32.row.col.f32.e4m3.e4m3.f32 "
        "{%0,%1,%2,%3}, {%4,%5,%6,%7}, {%8,%9}, {%0,%1,%2,%3};"
        : "+f"(d[0]), "+f"(d[1]), "+f"(d[2]), "+f"(d[3])
        : "r"(a[0]), "r"(a[1]), "r"(a[2]), "r"(a[3]), "r"(b[0]), "r"(b[1]));
}

// A-pack address: byte offset for element (row, k) of the 1024x512 fp8 A matrix.
// 16B unit = one thread's {a0,a1,a2,a3} fragment for a (16row x 32k) block.
__device__ __forceinline__ uint32_t a_pack_byte(int row, int k) {
    int row16 = row >> 4, rl = row & 15, half = rl >> 3, l4 = rl & 7;
    int kblk = k >> 5, kk = k & 31, q = kk >> 4, lm = (kk >> 2) & 3, b = kk & 3;
    int lane = l4 * 4 + lm;
    return ((uint32_t)((row16 * 16 + kblk) * 32 + lane)) * 16 + q * 8 + half * 4 + b;
}
// B-pack address: byte offset for element (col, k). 8B unit per lane per (8col x 32k) block.
__device__ __forceinline__ uint32_t b_pack_byte(int col, int k) {
    int col8 = col >> 3, l4 = col & 7;
    int kblk = k >> 5, kk = k & 31, q = kk >> 4, lm = (kk >> 2) & 3, b = kk & 3;
    int lane = l4 * 4 + lm;
    return ((uint32_t)((col8 * 16 + kblk) * 32 + lane)) * 8 + q * 4 + b;
}

// ---------------------------------------------------------------------------
// Kernel 1: normalize feats rows -> fp32 + packed e4m3(x16). grid=1024 x 128.
__global__ void k_norm_feats(const float* __restrict__ feats) {
    int row = blockIdx.x;
    int t = threadIdx.x;
    const float2* x = (const float2*)(feats + row * DIM);
    float2 v[2];
    v[0] = x[t]; v[1] = x[t + 128];
    float ss = v[0].x * v[0].x + v[0].y * v[0].y + v[1].x * v[1].x + v[1].y * v[1].y;
#pragma unroll
    for (int off = 16; off > 0; off >>= 1) ss += __shfl_xor_sync(0xffffffffu, ss, off);
    __shared__ float sred[4];
    __shared__ float srinv;
    int lane = t & 31, wp = t >> 5;
    if (lane == 0) sred[wp] = ss;
    __syncthreads();
    if (t == 0) {
        float tot = sred[0] + sred[1] + sred[2] + sred[3];
        srinv = 1.f / fmaxf(sqrtf(tot), 1e-12f);
    }
    __syncthreads();
    float rinv = srinv;
#pragma unroll
    for (int i = 0; i < 2; i++) {
        int j = t + i * 128;          // float2 index; k = 2j, 2j+1
        float yx = v[i].x * rinv, yy = v[i].y * rinv;
        g_fn[row * DIM + 2 * j] = yx;
        g_fn[row * DIM + 2 * j + 1] = yy;
        uint32_t ba = a_pack_byte(row, 2 * j);   // even k -> ushort-aligned
        g_fnb8[ba >> 1] = cvt_e4m3x2(yy * FP8_SCALE, yx * FP8_SCALE);
    }
}

// ---------------------------------------------------------------------------
// Kernel 2: normalize W rows -> packed e4m3(x16) + winv. One warp per row.
__global__ void k_wnorm(const float* __restrict__ w) {
    int wp = threadIdx.x >> 5, lane = threadIdx.x & 31;
    int row = blockIdx.x * 8 + wp;
    if (row >= NCLS) return;
    const float2* x = (const float2*)(w + (size_t)row * DIM);
    float2 v[8];
    float ss = 0.f;
#pragma unroll
    for (int i = 0; i < 8; i++) {
        v[i] = x[lane + i * 32];
        ss += v[i].x * v[i].x + v[i].y * v[i].y;
    }
#pragma unroll
    for (int off = 16; off > 0; off >>= 1) ss += __shfl_xor_sync(0xffffffffu, ss, off);
    float rinv = 1.f / fmaxf(sqrtf(ss), 1e-12f);
    float rs16 = rinv * FP8_SCALE;
#pragma unroll
    for (int i = 0; i < 8; i++) {
        int k0 = 2 * (lane + i * 32);
        uint32_t bb = b_pack_byte(row, k0);
        g_wnb8[bb >> 1] = cvt_e4m3x2(v[i].y * rs16, v[i].x * rs16);
    }
    if (lane == 0) g_winv[row] = rinv;
}

// ---------------------------------------------------------------------------
// Kernel 3: fp8 mma GEMM, B-resident, packed fragments, K=128 A chunks.
// 256 threads = 8 warps (2M x 4N); warp tile 64 x (TN*8); m16n8k32.
#define OFF_RED 0        // 512 floats
#define OFF_LAB 2048     // 128 ints
#define OFF_A0  2560     // 16 KB
#define OFF_A1  18944    // 16 KB
#define OFF_B   35328    // TN*16 KB resident

template <int TN>
__global__ void __launch_bounds__(256, 1)
k_main_fp8(const int* __restrict__ labels, int colBase0, int slotBase) {
    extern __shared__ char sm[];
    float* s_red = (float*)sm;
    int* s_lab = (int*)(sm + OFF_LAB);
    const uint32_t sb = smem_u32(sm);
    const uint32_t aBuf[2] = { sb + OFF_A0, sb + OFF_A1 };
    const char* sAc[2] = { sm + OFF_A0, sm + OFF_A1 };
    const char* sBc = sm + OFF_B;

    const int tid = threadIdx.x;
    const int wid = tid >> 5, lane = tid & 31;
    const int l4 = lane >> 2, lm = lane & 3;
    const int warpM = (wid & 1) * 64;           // 0 or 64
    const int warpN = (wid >> 1) * (TN * 8);
    const int mbBase = warpM >> 4;              // 0 or 4
    const int nbBase = warpN >> 3;              // (wid>>1)*TN
    const int colBase = colBase0 + blockIdx.x * (TN * 32);
    const int slot = slotBase + blockIdx.x;

    // ---- B resident: contiguous packed stripe, TN*16 KB ----
    {
        const char* wsrc = (const char*)g_wnb8 + (size_t)(colBase >> 3) * 4096;
#pragma unroll
        for (int i = 0; i < TN * 4; i++) {
            int idx = tid + i * 256;
            cp16(sb + OFF_B + (uint32_t)idx * 16, wsrc + (size_t)idx * 16);
        }
        asm volatile("cp.async.commit_group;" ::: "memory");
    }

    // ---- A chunk loader: it = mt*4 + kc covers rows mt*128.., K kc*128.. ----
    auto loadA = [&](int it, int buf) {
        int mt = it >> 2, kc = it & 3;
        const char* asrc = (const char*)g_fnb8;
#pragma unroll
        for (int i = 0; i < 4; i++) {
            int idx = tid + i * 256;              // 0..1023
            int seg = idx >> 7;                   // row16 local 0..7
            cp16(aBuf[buf] + (uint32_t)idx * 16,
                 asrc + (size_t)(mt * 8 + seg) * 8192 + kc * 2048 + (idx & 127) * 16);
        }
        asm volatile("cp.async.commit_group;" ::: "memory");
    };
    loadA(0, 0);

    float acc[4][TN][4];
#pragma unroll
    for (int i = 0; i < 4; i++)
#pragma unroll
        for (int j = 0; j < TN; j++)
#pragma unroll
            for (int e = 0; e < 4; e++) acc[i][j][e] = 0.f;

#pragma unroll 1
    for (int it = 0; it < 32; it++) {
        const int kc = it & 3;
        if (it + 1 < 32) {
            loadA(it + 1, (it + 1) & 1);
            asm volatile("cp.async.wait_group 1;" ::: "memory");
        } else {
            asm volatile("cp.async.wait_group 0;" ::: "memory");
        }
        __syncthreads();
        if (kc == 0 && tid < 128) s_lab[tid] = labels[(it >> 2) * 128 + tid];

        const char* A = sAc[it & 1];
#pragma unroll
        for (int ks = 0; ks < 4; ks++) {
            uint32_t af[4][4], bf[TN][2];
#pragma unroll
            for (int tm = 0; tm < 4; tm++) {
                uint4 t4 = *(const uint4*)(A + ((mbBase + tm) * 4 + ks) * 512 + lane * 16);
                af[tm][0] = t4.x; af[tm][1] = t4.y; af[tm][2] = t4.z; af[tm][3] = t4.w;
            }
#pragma unroll
            for (int tn = 0; tn < TN; tn++) {
                uint2 t2 = *(const uint2*)(sBc + (size_t)((nbBase + tn) * 16 + kc * 4 + ks) * 256 + lane * 8);
                bf[tn][0] = t2.x; bf[tn][1] = t2.y;
            }
#pragma unroll
            for (int tm = 0; tm < 4; tm++)
#pragma unroll
                for (int tn = 0; tn < TN; tn++)
                    mma_fp8(acc[tm][tn], af[tm], bf[tn]);
        }
        __syncthreads();

        // ---- per-M-tile epilogue ----
        if (kc == 3) {
            const int rowBase = (it >> 2) * 128;
            float rs[4][2];
#pragma unroll
            for (int tm = 0; tm < 4; tm++) { rs[tm][0] = 0.f; rs[tm][1] = 0.f; }
#pragma unroll
            for (int tn = 0; tn < TN; tn++) {
                int lc = warpN + tn * 8 + 2 * lm;
                int gc0 = colBase + lc, gc1 = gc0 + 1;
                float m0 = (gc0 < NCLS) ? 1.f : 0.f;
                float m1 = (gc1 < NCLS) ? 1.f : 0.f;
#pragma unroll
                for (int tm = 0; tm < 4; tm++) {
                    int r0 = warpM + tm * 16 + l4;
                    int r1 = r0 + 8;
                    // logit = 64*cos = acc * 0.25 (acc = 256*cos); clamp [-64,64]
                    float c0 = fminf(fmaxf(acc[tm][tn][0] * 0.25f, -64.f), 64.f);
                    float c1 = fminf(fmaxf(acc[tm][tn][1] * 0.25f, -64.f), 64.f);
                    float c2 = fminf(fmaxf(acc[tm][tn][2] * 0.25f, -64.f), 64.f);
                    float c3 = fminf(fmaxf(acc[tm][tn][3] * 0.25f, -64.f), 64.f);
                    if (gc0 == s_lab[r0]) g_cosl[rowBase + r0] = c0;
                    if (gc1 == s_lab[r0]) g_cosl[rowBase + r0] = c1;
                    if (gc0 == s_lab[r1]) g_cosl[rowBase + r1] = c2;
                    if (gc1 == s_lab[r1]) g_cosl[rowBase + r1] = c3;
                    rs[tm][0] += m0 * __expf(c0 - 64.f) + m1 * __expf(c1 - 64.f);
                    rs[tm][1] += m0 * __expf(c2 - 64.f) + m1 * __expf(c3 - 64.f);
                    acc[tm][tn][0] = 0.f; acc[tm][tn][1] = 0.f;
                    acc[tm][tn][2] = 0.f; acc[tm][tn][3] = 0.f;
                }
            }
#pragma unroll
            for (int tm = 0; tm < 4; tm++)
#pragma unroll
                for (int h = 0; h < 2; h++) {
                    float v = rs[tm][h];
                    v += __shfl_xor_sync(0xffffffffu, v, 1);
                    v += __shfl_xor_sync(0xffffffffu, v, 2);
                    rs[tm][h] = v;
                }
            if (lm == 0) {
                int wn = wid >> 1;
#pragma unroll
                for (int tm = 0; tm < 4; tm++) {
                    int r0 = warpM + tm * 16 + l4;
                    s_red[wn * 128 + r0] = rs[tm][0];
                    s_red[wn * 128 + r0 + 8] = rs[tm][1];
                }
            }
            __syncthreads();
            if (tid < 128) {
                float s = s_red[tid] + s_red[128 + tid] + s_red[256 + tid] + s_red[384 + tid];
                g_partial[slot * NROWS + rowBase + tid] = s;
            }
        }
    }
}

// ---------------------------------------------------------------------------
// Kernel 4: exact fp32 label cos -> margin target.
__global__ void k_label(const float* __restrict__ w, const int* __restrict__ labels) {
    int wp = threadIdx.x >> 5, lane = threadIdx.x & 31;
    int n = blockIdx.x * 8 + wp;
    if (n >= NROWS) return;
    int lab = labels[n];
    const float* fr = g_fn + n * DIM;
    const float* wr = w + (size_t)lab * DIM;
    float dot = 0.f;
#pragma unroll
    for (int i = 0; i < 16; i++) dot += fr[lane + i * 32] * wr[lane + i * 32];
#pragma unroll
    for (int off = 16; off > 0; off >>= 1) dot += __shfl_xor_sync(0xffffffffu, dot, off);
    if (lane == 0) {
        float cosv = fminf(fmaxf(dot * g_winv[lab], -1.f), 1.f);
        float sinv = sqrtf(1.f - cosv * cosv + 1e-5f);
        float cm = cosv * COS_M - sinv * SIN_M;
        g_tgt[n] = (cosv > MIN_COS) ? cm : (cosv - sinv * MARG);
    }
}

// ---------------------------------------------------------------------------
// Kernel 5: merge partials, exact label swap, NLL, mean.
__global__ void k_final(float* __restrict__ out) {
    int t = threadIdx.x;
    float s = 0.f;
    for (int cb = 0; cb < NSLOTS; cb++) s += g_partial[cb * NROWS + t];
    float cl = g_cosl[t];                        // label logit actually inside s
    float tgt = g_tgt[t];
    float s2 = s - expf(cl - 64.f) + expf(SCALE * tgt - 64.f);
    float nll = 64.f + logf(s2) - SCALE * tgt;

    __shared__ float sred[1024];
    sred[t] = nll;
    __syncthreads();
    for (int off = 512; off > 0; off >>= 1) {
        if (t < off) sred[t] += sred[t + off];
        __syncthreads();
    }
    if (t == 0) out[0] = sred[0] * (1.0f / (float)NROWS);
}

// ---------------------------------------------------------------------------
#define SMEM8 (OFF_B + 8 * 16384)   // 166400
#define SMEM6 (OFF_B + 6 * 16384)   // 133632

extern "C" void kernel_launch(void* const* d_in, const int* in_sizes, int n_in,
                              void* d_out, int out_size) {
    const float* feats = (const float*)d_in[0];
    const float* w = (const float*)d_in[1];
    const int* labels = (const int*)d_in[2];
    float* out = (float*)d_out;

    cudaFuncSetAttribute(k_main_fp8<8>, cudaFuncAttributeMaxDynamicSharedMemorySize, SMEM8);
    cudaFuncSetAttribute(k_main_fp8<6>, cudaFuncAttributeMaxDynamicSharedMemorySize, SMEM6);

    k_norm_feats<<<NROWS, 128>>>(feats);
    k_wnorm<<<(NCLS + 7) / 8, 256>>>(w);
    // 296 CTAs x 256 cols = 75776, then 148 CTAs x 192 cols = 28416 (>= 100000)
    k_main_fp8<8><<<296, 256, SMEM8>>>(labels, 0, 0);
    k_main_fp8<6><<<148, 256, SMEM6>>>(labels, 75776, 296);
    k_label<<<NROWS / 8, 256>>>(w, labels);
    k_final<<<1, 1024>>>(out);
}